// round 1
// baseline (speedup 1.0000x reference)
#include <cuda_runtime.h>

#define BTOK 8192
#define IND  1024
#define HID  4096
#define OUTD 1024
#define RHD  128
#define NE   3
#define GCAP 8448            // max padded gathered rows (multiple of 128)
#define MTILES (GCAP / 128)  // 66

// ---------------- device scratch (static: allocation-free) ----------------
__device__ int   g_selected[BTOK];
__device__ int   g_counts[NE];
__device__ int   g_cursor[NE];
__device__ int   g_off[NE + 1];   // padded segment offsets
__device__ int   g_total;         // total padded rows (multiple of 128)
__device__ int   g_gathered[GCAP];
__device__ float g_rh[BTOK * RHD];
__device__ float g_h[(size_t)GCAP * HID];  // 138 MB hidden scratch

// ---------------- init ----------------
__global__ void k_init() {
    int i = blockIdx.x * blockDim.x + threadIdx.x;
    if (i < GCAP) g_gathered[i] = -1;
    if (i < NE) { g_counts[i] = 0; g_cursor[i] = 0; }
}

// ---------------- generic 128x128x16 fp32 tiled GEMM ----------------
// C[m,n] = epilogue( sum_k A[m,k]*B[k,n] + bias[n] )
// GATHER:  A row index comes from g_gathered (x rows); -1 => zero row
// A_IS_H:  A is the g_h scratch (row stride LDA)
// C_SEL:   0 = Cdst param, 1 = g_rh, 2 = g_h
// SCATTER: C row index via g_gathered (skip -1)
// EXPERT:  blockIdx.y tile mapped to expert via padded offsets; B/bias offset by expert
template<int K, int LDA, int N, int LDC,
         bool GATHER, bool A_IS_H, int C_SEL, bool RELU_EPI, bool SCATTER, bool EXPERT>
__global__ __launch_bounds__(256)
void gemm128(const float* __restrict__ Asrc, const float* __restrict__ Bsrc,
             const float* __restrict__ bias, float* __restrict__ Cdst, int Mfixed)
{
    const int BM = 128, BN = 128, BK = 16;
    __shared__ float As[BK][BM];
    __shared__ float Bs[BK][BN];

    const int mtile = blockIdx.y;
    const int m0 = mtile * BM;

    if (EXPERT) {
        int total = g_total;
        if (m0 >= total) return;
        int e = 0;
        if (m0 >= g_off[1]) e = (m0 >= g_off[2]) ? 2 : 1;
        Bsrc += (size_t)e * K * N;
        bias += (size_t)e * N;
    } else {
        if (m0 >= Mfixed) return;
    }
    const int n0 = blockIdx.x * BN;
    const int tid = threadIdx.x;

    const float* Ab = A_IS_H ? (const float*)g_h : Asrc;

    // Precompute A row pointers: each thread loads rows (tid/4) and (tid/4 + 64)
    const float* arow[2];
#pragma unroll
    for (int t = 0; t < 2; t++) {
        int lin = tid + t * 256;
        int row = lin >> 2;
        int r;
        if (GATHER) r = g_gathered[m0 + row];
        else        r = m0 + row;
        arow[t] = (r >= 0) ? (Ab + (size_t)r * LDA) : (const float*)0;
    }

    float c[8][8];
#pragma unroll
    for (int i = 0; i < 8; i++)
#pragma unroll
        for (int j = 0; j < 8; j++) c[i][j] = 0.f;

    const int tx = tid & 15;   // n-group
    const int ty = tid >> 4;   // m-group

    for (int k0 = 0; k0 < K; k0 += BK) {
        // --- load A tile (128 rows x 16 k), store transposed As[k][m] ---
#pragma unroll
        for (int t = 0; t < 2; t++) {
            int lin = tid + t * 256;
            int row = lin >> 2;
            int kq  = (lin & 3) * 4;
            float4 v = make_float4(0.f, 0.f, 0.f, 0.f);
            if (arow[t]) v = *reinterpret_cast<const float4*>(arow[t] + k0 + kq);
            As[kq + 0][row] = v.x;
            As[kq + 1][row] = v.y;
            As[kq + 2][row] = v.z;
            As[kq + 3][row] = v.w;
        }
        // --- load B tile (16 k x 128 n) ---
#pragma unroll
        for (int t = 0; t < 2; t++) {
            int lin = tid + t * 256;
            int kk = lin >> 5;
            int nq = (lin & 31) * 4;
            float4 v = *reinterpret_cast<const float4*>(Bsrc + (size_t)(k0 + kk) * N + n0 + nq);
            *reinterpret_cast<float4*>(&Bs[kk][nq]) = v;
        }
        __syncthreads();

#pragma unroll
        for (int kk = 0; kk < BK; kk++) {
            float a[8], b[8];
            float4 a0 = *reinterpret_cast<const float4*>(&As[kk][ty * 8]);
            float4 a1 = *reinterpret_cast<const float4*>(&As[kk][ty * 8 + 4]);
            float4 b0 = *reinterpret_cast<const float4*>(&Bs[kk][tx * 8]);
            float4 b1 = *reinterpret_cast<const float4*>(&Bs[kk][tx * 8 + 4]);
            a[0]=a0.x; a[1]=a0.y; a[2]=a0.z; a[3]=a0.w;
            a[4]=a1.x; a[5]=a1.y; a[6]=a1.z; a[7]=a1.w;
            b[0]=b0.x; b[1]=b0.y; b[2]=b0.z; b[3]=b0.w;
            b[4]=b1.x; b[5]=b1.y; b[6]=b1.z; b[7]=b1.w;
#pragma unroll
            for (int i = 0; i < 8; i++)
#pragma unroll
                for (int j = 0; j < 8; j++)
                    c[i][j] = fmaf(a[i], b[j], c[i][j]);
        }
        __syncthreads();
    }

    // --- epilogue ---
    float* Cbase = (C_SEL == 0) ? Cdst : (C_SEL == 1 ? (float*)g_rh : (float*)g_h);
    float bv[8];
#pragma unroll
    for (int j = 0; j < 8; j++) bv[j] = bias[n0 + tx * 8 + j];

#pragma unroll
    for (int i = 0; i < 8; i++) {
        int row = m0 + ty * 8 + i;
        int r = row;
        if (SCATTER) {
            r = g_gathered[row];
            if (r < 0) continue;
        }
        float* cp = Cbase + (size_t)r * LDC + n0 + tx * 8;
        float o[8];
#pragma unroll
        for (int j = 0; j < 8; j++) {
            float v = c[i][j] + bv[j];
            o[j] = RELU_EPI ? fmaxf(v, 0.f) : v;
        }
        *reinterpret_cast<float4*>(cp)     = make_float4(o[0], o[1], o[2], o[3]);
        *reinterpret_cast<float4*>(cp + 4) = make_float4(o[4], o[5], o[6], o[7]);
    }
}

// ---------------- logits + argmax + counts ----------------
__global__ void k_logits(const float* __restrict__ w2, const float* __restrict__ b2)
{
    __shared__ float w2s[RHD * NE];
    __shared__ float b2s[NE];
    int tid = threadIdx.x;  // 128 threads
    for (int i = tid; i < RHD * NE; i += 128) w2s[i] = w2[i];
    if (tid < NE) b2s[tid] = b2[tid];
    __syncthreads();

    int token = blockIdx.x * 128 + tid;
    if (token >= BTOK) return;
    const float* rh = g_rh + (size_t)token * RHD;
    float a0 = b2s[0], a1 = b2s[1], a2 = b2s[2];
#pragma unroll 8
    for (int k = 0; k < RHD; k++) {
        float v = rh[k];
        a0 = fmaf(v, w2s[k * NE + 0], a0);
        a1 = fmaf(v, w2s[k * NE + 1], a1);
        a2 = fmaf(v, w2s[k * NE + 2], a2);
    }
    int sel = 0; float best = a0;
    if (a1 > best) { best = a1; sel = 1; }
    if (a2 > best) { best = a2; sel = 2; }
    g_selected[token] = sel;
    atomicAdd(&g_counts[sel], 1);
}

// ---------------- padded segment offsets ----------------
__global__ void k_offsets()
{
    int off = 0;
    g_off[0] = 0;
    for (int e = 0; e < NE; e++) {
        int mpad = ((g_counts[e] + 127) / 128) * 128;
        off += mpad;
        g_off[e + 1] = off;
    }
    g_total = off;
}

// ---------------- scatter token ids into per-expert segments ----------------
__global__ void k_scatter()
{
    int b = blockIdx.x * 256 + threadIdx.x;
    if (b >= BTOK) return;
    int e = g_selected[b];
    int pos = atomicAdd(&g_cursor[e], 1);
    g_gathered[g_off[e] + pos] = b;
}

// ---------------- routing stats to output tail ----------------
__global__ void k_stats(float* out, int out_size)
{
    int i = threadIdx.x;
    if (i < NE && out_size >= BTOK * OUTD + NE)
        out[(size_t)BTOK * OUTD + i] = (float)g_counts[i];
}

// ---------------- launch ----------------
extern "C" void kernel_launch(void* const* d_in, const int* in_sizes, int n_in,
                              void* d_out, int out_size)
{
    const float* x   = (const float*)d_in[0];
    const float* rw1 = (const float*)d_in[1];
    const float* rb1 = (const float*)d_in[2];
    const float* rw2 = (const float*)d_in[3];
    const float* rb2 = (const float*)d_in[4];
    const float* ew1 = (const float*)d_in[5];
    const float* eb1 = (const float*)d_in[6];
    const float* ew2 = (const float*)d_in[7];
    const float* eb2 = (const float*)d_in[8];
    float* out = (float*)d_out;

    (void)in_sizes; (void)n_in;

    k_init<<<(GCAP + 255) / 256, 256>>>();

    // Router hidden: rh = relu(x @ rw1 + rb1)   [8192 x 128]
    gemm128<1024, 1024, 128, 128, false, false, 1, true, false, false>
        <<<dim3(1, BTOK / 128), 256>>>(x, rw1, rb1, nullptr, BTOK);

    k_logits<<<BTOK / 128, 128>>>(rw2, rb2);
    k_offsets<<<1, 1>>>();
    k_scatter<<<BTOK / 256, 256>>>();

    // Expert GEMM1: h = relu(Xg @ W1[e] + b1[e])   [total x 4096]
    gemm128<1024, 1024, 4096, 4096, true, false, 2, true, false, true>
        <<<dim3(HID / 128, MTILES), 256>>>(x, ew1, eb1, nullptr, 0);

    // Expert GEMM2: y = h @ W2[e] + b2[e], scatter to out[token]
    gemm128<4096, 4096, 1024, 1024, false, true, 0, false, true, true>
        <<<dim3(OUTD / 128, MTILES), 256>>>(nullptr, ew2, eb2, out, 0);

    k_stats<<<1, 32>>>(out, out_size);
}

// round 9
// speedup vs baseline: 3.7914x; 3.7914x over previous
#include <cuda_runtime.h>
#include <cuda_fp16.h>
#include <mma.h>

using namespace nvcuda;

#define BTOK 8192
#define IND  1024
#define HID  4096
#define OUTD 1024
#define RHD  128
#define NE   3
#define GCAP 8448            // max padded gathered rows (multiple of 128)
#define MTILES (GCAP / 128)  // 66

// ---------------- device scratch (identical set to round 1) ----------------
__device__ int   g_selected[BTOK];
__device__ int   g_counts[NE];
__device__ int   g_cursor[NE];
__device__ int   g_off[NE + 1];
__device__ int   g_total;
__device__ int   g_gathered[GCAP];
__device__ float g_rh[BTOK * RHD];
__device__ float g_h[(size_t)GCAP * HID];  // 138 MB hidden scratch (fp32)

// ---------------- init ----------------
__global__ void k_init() {
    int i = blockIdx.x * blockDim.x + threadIdx.x;
    if (i < GCAP) g_gathered[i] = -1;
    if (i < NE) { g_counts[i] = 0; g_cursor[i] = 0; }
}

// ---------------- round-1 fp32 SIMT GEMM (used for the router only) ----------------
template<int K, int LDA, int N, int LDC,
         bool GATHER, bool A_IS_H, int C_SEL, bool RELU_EPI, bool SCATTER, bool EXPERT>
__global__ __launch_bounds__(256)
void gemm128(const float* __restrict__ Asrc, const float* __restrict__ Bsrc,
             const float* __restrict__ bias, float* __restrict__ Cdst, int Mfixed)
{
    const int BM = 128, BN = 128, BK = 16;
    __shared__ float As[BK][BM];
    __shared__ float Bs[BK][BN];

    const int mtile = blockIdx.y;
    const int m0 = mtile * BM;

    if (EXPERT) {
        int total = g_total;
        if (m0 >= total) return;
        int e = 0;
        if (m0 >= g_off[1]) e = (m0 >= g_off[2]) ? 2 : 1;
        Bsrc += (size_t)e * K * N;
        bias += (size_t)e * N;
    } else {
        if (m0 >= Mfixed) return;
    }
    const int n0 = blockIdx.x * BN;
    const int tid = threadIdx.x;

    const float* Ab = A_IS_H ? (const float*)g_h : Asrc;

    const float* arow[2];
#pragma unroll
    for (int t = 0; t < 2; t++) {
        int lin = tid + t * 256;
        int row = lin >> 2;
        int r;
        if (GATHER) r = g_gathered[m0 + row];
        else        r = m0 + row;
        arow[t] = (r >= 0) ? (Ab + (size_t)r * LDA) : (const float*)0;
    }

    float c[8][8];
#pragma unroll
    for (int i = 0; i < 8; i++)
#pragma unroll
        for (int j = 0; j < 8; j++) c[i][j] = 0.f;

    const int tx = tid & 15;
    const int ty = tid >> 4;

    for (int k0 = 0; k0 < K; k0 += BK) {
#pragma unroll
        for (int t = 0; t < 2; t++) {
            int lin = tid + t * 256;
            int row = lin >> 2;
            int kq  = (lin & 3) * 4;
            float4 v = make_float4(0.f, 0.f, 0.f, 0.f);
            if (arow[t]) v = *reinterpret_cast<const float4*>(arow[t] + k0 + kq);
            As[kq + 0][row] = v.x;
            As[kq + 1][row] = v.y;
            As[kq + 2][row] = v.z;
            As[kq + 3][row] = v.w;
        }
#pragma unroll
        for (int t = 0; t < 2; t++) {
            int lin = tid + t * 256;
            int kk = lin >> 5;
            int nq = (lin & 31) * 4;
            float4 v = *reinterpret_cast<const float4*>(Bsrc + (size_t)(k0 + kk) * N + n0 + nq);
            *reinterpret_cast<float4*>(&Bs[kk][nq]) = v;
        }
        __syncthreads();

#pragma unroll
        for (int kk = 0; kk < BK; kk++) {
            float a[8], b[8];
            float4 a0 = *reinterpret_cast<const float4*>(&As[kk][ty * 8]);
            float4 a1 = *reinterpret_cast<const float4*>(&As[kk][ty * 8 + 4]);
            float4 b0 = *reinterpret_cast<const float4*>(&Bs[kk][tx * 8]);
            float4 b1 = *reinterpret_cast<const float4*>(&Bs[kk][tx * 8 + 4]);
            a[0]=a0.x; a[1]=a0.y; a[2]=a0.z; a[3]=a0.w;
            a[4]=a1.x; a[5]=a1.y; a[6]=a1.z; a[7]=a1.w;
            b[0]=b0.x; b[1]=b0.y; b[2]=b0.z; b[3]=b0.w;
            b[4]=b1.x; b[5]=b1.y; b[6]=b1.z; b[7]=b1.w;
#pragma unroll
            for (int i = 0; i < 8; i++)
#pragma unroll
                for (int j = 0; j < 8; j++)
                    c[i][j] = fmaf(a[i], b[j], c[i][j]);
        }
        __syncthreads();
    }

    float* Cbase = (C_SEL == 0) ? Cdst : (C_SEL == 1 ? (float*)g_rh : (float*)g_h);
    float bv[8];
#pragma unroll
    for (int j = 0; j < 8; j++) bv[j] = bias[n0 + tx * 8 + j];

#pragma unroll
    for (int i = 0; i < 8; i++) {
        int row = m0 + ty * 8 + i;
        int r = row;
        if (SCATTER) {
            r = g_gathered[row];
            if (r < 0) continue;
        }
        float* cp = Cbase + (size_t)r * LDC + n0 + tx * 8;
        float o[8];
#pragma unroll
        for (int j = 0; j < 8; j++) {
            float v = c[i][j] + bv[j];
            o[j] = RELU_EPI ? fmaxf(v, 0.f) : v;
        }
        *reinterpret_cast<float4*>(cp)     = make_float4(o[0], o[1], o[2], o[3]);
        *reinterpret_cast<float4*>(cp + 4) = make_float4(o[4], o[5], o[6], o[7]);
    }
}

// ---------------- WMMA fp16 expert GEMM (same structure as gemm128) ----------------
// Tiles converted fp32->fp16 at smem store; wmma 16x16x16 fp32 accumulate.
// As[k][m] = A col-major (LDS=136), Bs[k][n] = B row-major (LDS=136).
// 8 warps, warp tile 32x64 (2 m-frags x 4 n-frags).
template<int K, int LDA, int N, int LDC,
         bool GATHER, bool A_IS_H, int C_SEL, bool RELU_EPI, bool SCATTER>
__global__ __launch_bounds__(256)
void wgemm128(const float* __restrict__ Asrc, const float* __restrict__ Bsrc,
              const float* __restrict__ bias, float* __restrict__ Cdst)
{
    const int BK = 16, LDS = 136;
    __shared__ __align__(32) __half As[BK][LDS];
    __shared__ __align__(32) __half Bs[BK][LDS];
    __shared__ __align__(32) float stage[8][16][20];   // ld=20 floats (80B, mult of 16B)

    const int m0 = blockIdx.y * 128;
    if (m0 >= g_total) return;
    int e = 0;
    if (m0 >= g_off[1]) e = (m0 >= g_off[2]) ? 2 : 1;
    const float* Bp = Bsrc + (size_t)e * K * N;
    const float* bp = bias + (size_t)e * N;

    const int n0 = blockIdx.x * 128;
    const int tid = threadIdx.x;
    const int wid = tid >> 5, lane = tid & 31;
    const int wm = wid & 3, wn = wid >> 2;   // 4x2 warp grid, 32x64 warp tile

    const float* Ab = A_IS_H ? (const float*)g_h : Asrc;

    // per-thread load slots (identical mapping to gemm128)
    const float* arow[2];
    int akq[2];
#pragma unroll
    for (int t = 0; t < 2; t++) {
        int lin = tid + t * 256;
        int row = lin >> 2;
        akq[t] = (lin & 3) * 4;
        int r = GATHER ? g_gathered[m0 + row] : (m0 + row);
        arow[t] = (r >= 0) ? (Ab + (size_t)r * LDA) : (const float*)0;
    }
    int arowi[2] = { tid >> 2, (tid >> 2) + 64 };
    int bkk[2]   = { tid >> 5, (tid >> 5) + 8 };
    int bnq      = (tid & 31) * 4;

    wmma::fragment<wmma::accumulator, 16, 16, 16, float> cf[2][4];
#pragma unroll
    for (int i = 0; i < 2; i++)
#pragma unroll
        for (int j = 0; j < 4; j++) wmma::fill_fragment(cf[i][j], 0.f);

    // prefetch chunk 0
    float4 pa[2], pb[2];
#pragma unroll
    for (int t = 0; t < 2; t++) {
        pa[t] = arow[t] ? *reinterpret_cast<const float4*>(arow[t] + akq[t])
                        : make_float4(0.f, 0.f, 0.f, 0.f);
        pb[t] = *reinterpret_cast<const float4*>(Bp + (size_t)bkk[t] * N + n0 + bnq);
    }

    for (int k0 = 0; k0 < K; k0 += BK) {
        // store prefetched tile to smem (fp16 convert)
#pragma unroll
        for (int t = 0; t < 2; t++) {
            As[akq[t] + 0][arowi[t]] = __float2half_rn(pa[t].x);
            As[akq[t] + 1][arowi[t]] = __float2half_rn(pa[t].y);
            As[akq[t] + 2][arowi[t]] = __float2half_rn(pa[t].z);
            As[akq[t] + 3][arowi[t]] = __float2half_rn(pa[t].w);
            __half2 h01 = __floats2half2_rn(pb[t].x, pb[t].y);
            __half2 h23 = __floats2half2_rn(pb[t].z, pb[t].w);
            *reinterpret_cast<__half2*>(&Bs[bkk[t]][bnq])     = h01;
            *reinterpret_cast<__half2*>(&Bs[bkk[t]][bnq + 2]) = h23;
        }
        __syncthreads();

        // prefetch next chunk
        if (k0 + BK < K) {
#pragma unroll
            for (int t = 0; t < 2; t++) {
                pa[t] = arow[t] ? *reinterpret_cast<const float4*>(arow[t] + k0 + BK + akq[t])
                                : make_float4(0.f, 0.f, 0.f, 0.f);
                pb[t] = *reinterpret_cast<const float4*>(
                    Bp + (size_t)(k0 + BK + bkk[t]) * N + n0 + bnq);
            }
        }

        // compute: one k-fragment (BK=16)
        wmma::fragment<wmma::matrix_a, 16, 16, 16, __half, wmma::col_major> af[2];
        wmma::fragment<wmma::matrix_b, 16, 16, 16, __half, wmma::row_major> bf[4];
#pragma unroll
        for (int mf = 0; mf < 2; mf++)
            wmma::load_matrix_sync(af[mf], &As[0][wm * 32 + mf * 16], LDS);
#pragma unroll
        for (int nf = 0; nf < 4; nf++)
            wmma::load_matrix_sync(bf[nf], &Bs[0][wn * 64 + nf * 16], LDS);
#pragma unroll
        for (int mf = 0; mf < 2; mf++)
#pragma unroll
            for (int nf = 0; nf < 4; nf++)
                wmma::mma_sync(cf[mf][nf], af[mf], bf[nf], cf[mf][nf]);
        __syncthreads();
    }

    // ---------------- epilogue: per-warp 16x16 staging (ld=20, legal) ----------------
    float* Cbase = (C_SEL == 0) ? Cdst : (float*)g_h;
#pragma unroll
    for (int mf = 0; mf < 2; mf++)
#pragma unroll
        for (int nf = 0; nf < 4; nf++) {
            wmma::store_matrix_sync(&stage[wid][0][0], cf[mf][nf], 20, wmma::mem_row_major);
            __syncwarp();
            int rb = m0 + wm * 32 + mf * 16;
            int cb = n0 + wn * 64 + nf * 16;
#pragma unroll
            for (int i = 0; i < 8; i++) {
                int idx = lane + i * 32;
                int rr = idx >> 4, cc = idx & 15;
                int row = rb + rr;
                int col = cb + cc;
                float v = stage[wid][rr][cc] + bp[col];
                if (RELU_EPI) v = fmaxf(v, 0.f);
                int r = row;
                if (SCATTER) {
                    r = g_gathered[row];
                    if (r < 0) continue;
                }
                Cbase[(size_t)r * LDC + col] = v;
            }
            __syncwarp();
        }
}

// ---------------- logits + argmax + counts (round-1 verbatim) ----------------
__global__ void k_logits(const float* __restrict__ w2, const float* __restrict__ b2)
{
    __shared__ float w2s[RHD * NE];
    __shared__ float b2s[NE];
    int tid = threadIdx.x;
    for (int i = tid; i < RHD * NE; i += 128) w2s[i] = w2[i];
    if (tid < NE) b2s[tid] = b2[tid];
    __syncthreads();

    int token = blockIdx.x * 128 + tid;
    if (token >= BTOK) return;
    const float* rh = g_rh + (size_t)token * RHD;
    float a0 = b2s[0], a1 = b2s[1], a2 = b2s[2];
#pragma unroll 8
    for (int k = 0; k < RHD; k++) {
        float v = rh[k];
        a0 = fmaf(v, w2s[k * NE + 0], a0);
        a1 = fmaf(v, w2s[k * NE + 1], a1);
        a2 = fmaf(v, w2s[k * NE + 2], a2);
    }
    int sel = 0; float best = a0;
    if (a1 > best) { best = a1; sel = 1; }
    if (a2 > best) { best = a2; sel = 2; }
    g_selected[token] = sel;
    atomicAdd(&g_counts[sel], 1);
}

__global__ void k_offsets()
{
    int off = 0;
    g_off[0] = 0;
    for (int e = 0; e < NE; e++) {
        int mpad = ((g_counts[e] + 127) / 128) * 128;
        off += mpad;
        g_off[e + 1] = off;
    }
    g_total = off;
}

__global__ void k_scatter()
{
    int b = blockIdx.x * 256 + threadIdx.x;
    if (b >= BTOK) return;
    int e = g_selected[b];
    int pos = atomicAdd(&g_cursor[e], 1);
    g_gathered[g_off[e] + pos] = b;
}

__global__ void k_stats(float* out, int out_size)
{
    int i = threadIdx.x;
    if (i < NE && out_size >= BTOK * OUTD + NE)
        out[(size_t)BTOK * OUTD + i] = (float)g_counts[i];
}

// ---------------- launch ----------------
extern "C" void kernel_launch(void* const* d_in, const int* in_sizes, int n_in,
                              void* d_out, int out_size)
{
    const float* x   = (const float*)d_in[0];
    const float* rw1 = (const float*)d_in[1];
    const float* rb1 = (const float*)d_in[2];
    const float* rw2 = (const float*)d_in[3];
    const float* rb2 = (const float*)d_in[4];
    const float* ew1 = (const float*)d_in[5];
    const float* eb1 = (const float*)d_in[6];
    const float* ew2 = (const float*)d_in[7];
    const float* eb2 = (const float*)d_in[8];
    float* out = (float*)d_out;

    (void)in_sizes; (void)n_in;

    k_init<<<(GCAP + 255) / 256, 256>>>();

    // Router hidden: rh = relu(x @ rw1 + rb1)   [8192 x 128]  (fp32 SIMT, round-1)
    gemm128<1024, 1024, 128, 128, false, false, 1, true, false, false>
        <<<dim3(1, BTOK / 128), 256>>>(x, rw1, rb1, nullptr, BTOK);

    k_logits<<<BTOK / 128, 128>>>(rw2, rb2);
    k_offsets<<<1, 1>>>();
    k_scatter<<<BTOK / 256, 256>>>();

    // Expert GEMM1: h = relu(Xg @ W1[e] + b1[e])   [total x 4096]  (wmma fp16)
    wgemm128<1024, 1024, 4096, 4096, true, false, 2, true, false>
        <<<dim3(HID / 128, MTILES), 256>>>(x, ew1, eb1, nullptr);

    // Expert GEMM2: y = h @ W2[e] + b2[e], scatter to out[token]  (wmma fp16)
    wgemm128<4096, 4096, 1024, 1024, false, true, 0, false, true>
        <<<dim3(OUTD / 128, MTILES), 256>>>(nullptr, ew2, eb2, out);

    k_stats<<<1, 32>>>(out, out_size);
}